// round 1
// baseline (speedup 1.0000x reference)
#include <cuda_runtime.h>
#include <cuda_bf16.h>

// RoadGNN: GCN(2->32) -> ReLU -> GAT(32->2x32, mean heads) -> ReLU -> GCN(32->1)
// N=100000 nodes, E=1600000 edges. All scatter phases use fp32 atomics to L2.

#define MAXN 100000
#define MAXE 1600000

// ---------------- scratch (device globals; no allocations) ----------------
__device__ int      g_deg[MAXN];
__device__ float    g_dinv[MAXN];
__device__ float    g_hs[MAXN * 32];      // dinv[n] * (x@W1)[n]
__device__ float    g_acc1[MAXN * 32];    // GCN1 scatter accumulator
__device__ float    g_hg[MAXN * 64];      // GAT linear output [N, 2*32]
__device__ float    g_asrc[MAXN * 2];
__device__ float    g_adst[MAXN * 2];
__device__ unsigned g_menc[MAXN * 2];     // segment max, order-encoded float
__device__ float    g_s[MAXN * 2];        // softmax denominators (edge part)
__device__ float    g_accmsg[MAXN * 64];  // GAT message accumulator
__device__ float    g_z[MAXN];            // dinv[n] * (h2 @ W2)[n]
__device__ float    g_accz[MAXN];         // GCN2 scatter accumulator
__device__ int      g_is64;               // edge_index dtype flag

// ---------------- helpers ----------------
__device__ __forceinline__ unsigned encf(float f) {
    unsigned u = __float_as_uint(f);
    return (u & 0x80000000u) ? ~u : (u | 0x80000000u);
}
__device__ __forceinline__ float decf(unsigned u) {
    return __uint_as_float((u & 0x80000000u) ? (u & 0x7fffffffu) : ~u);
}
__device__ __forceinline__ float lrelu(float v) { return v > 0.f ? v : 0.2f * v; }

__device__ __forceinline__ void load_edge(const void* ei, int e, int E, int& r, int& c) {
    if (g_is64) {
        const long long* p = (const long long*)ei;
        r = (int)p[e]; c = (int)p[E + e];
    } else {
        const int* p = (const int*)ei;
        r = p[e]; c = p[E + e];
    }
}

// ---------------- kernels ----------------

// Detect int64 vs int32 edge_index: int64 nonneg < 2^31 => every odd int32 word is 0.
__global__ void k_detect(const int* __restrict__ ei32) {
    if (threadIdx.x == 0) {
        int is64 = 1;
        for (int i = 0; i < 64; i++)
            if (ei32[2 * i + 1] != 0) { is64 = 0; break; }
        g_is64 = is64;
    }
}

__global__ void k_zero(int n) {
    int gid = blockIdx.x * blockDim.x + threadIdx.x;
    if (gid < n * 64) g_accmsg[gid] = 0.f;
    if (gid < n * 32) g_acc1[gid] = 0.f;
    if (gid < n * 2)  g_s[gid] = 0.f;
    if (gid < n)      { g_deg[gid] = 1; g_accz[gid] = 0.f; }
}

__global__ void k_degcount(const void* __restrict__ ei, int E) {
    int e = blockIdx.x * blockDim.x + threadIdx.x;
    if (e >= E) return;
    int r, c; load_edge(ei, e, E, r, c);
    atomicAdd(&g_deg[c], 1);
}

// per-(node,channel): dinv, h_pre = x@W1, hs = dinv*h_pre
__global__ void k_node1(const float* __restrict__ x, const float* __restrict__ W1, int n) {
    int gid = blockIdx.x * blockDim.x + threadIdx.x;
    if (gid >= n * 32) return;
    int node = gid >> 5, k = gid & 31;
    float d = rsqrtf((float)g_deg[node]);
    if (k == 0) g_dinv[node] = d;
    float hp = fmaf(x[2 * node], W1[k], x[2 * node + 1] * W1[32 + k]);
    g_hs[gid] = d * hp;
}

// warp per edge: acc1[col] += hs[row]
__global__ void k_gcn1_edge(const void* __restrict__ ei, int E) {
    int gid = blockIdx.x * blockDim.x + threadIdx.x;
    int ed = gid >> 5, k = gid & 31;
    if (ed >= E) return;
    int r, c; load_edge(ei, ed, E, r, c);
    atomicAdd(&g_acc1[c * 32 + k], g_hs[r * 32 + k]);
}

// warp per node: finalize GCN1 (+relu), compute hg = h1@Wg, a_src/a_dst, init menc with self-loop e
__global__ void k_gat_node(const float* __restrict__ Wg, const float* __restrict__ b1,
                           const float* __restrict__ attS, const float* __restrict__ attD, int n) {
    __shared__ float sWg[32 * 64];
    int tid = threadIdx.x;
    for (int i = tid; i < 2048; i += blockDim.x) sWg[i] = Wg[i];
    __syncthreads();
    int warp = (blockIdx.x * blockDim.x + tid) >> 5;
    int lane = tid & 31;
    if (warp >= n) return;
    int node = warp;
    float d = g_dinv[node];
    float h1v = fmaxf(fmaf(d, g_acc1[node * 32 + lane] + g_hs[node * 32 + lane], b1[lane]), 0.f);
    float o0 = 0.f, o1 = 0.f;
#pragma unroll
    for (int i = 0; i < 32; i++) {
        float hv = __shfl_sync(0xffffffffu, h1v, i);
        o0 = fmaf(hv, sWg[i * 64 + lane], o0);
        o1 = fmaf(hv, sWg[i * 64 + 32 + lane], o1);
    }
    g_hg[node * 64 + lane]      = o0;
    g_hg[node * 64 + 32 + lane] = o1;
    float as0 = o0 * attS[lane];
    float as1 = o1 * attS[32 + lane];
    float ad0 = o0 * attD[lane];
    float ad1 = o1 * attD[32 + lane];
#pragma unroll
    for (int off = 16; off; off >>= 1) {
        as0 += __shfl_down_sync(0xffffffffu, as0, off);
        as1 += __shfl_down_sync(0xffffffffu, as1, off);
        ad0 += __shfl_down_sync(0xffffffffu, ad0, off);
        ad1 += __shfl_down_sync(0xffffffffu, ad1, off);
    }
    if (lane == 0) {
        g_asrc[node * 2]     = as0;
        g_asrc[node * 2 + 1] = as1;
        g_adst[node * 2]     = ad0;
        g_adst[node * 2 + 1] = ad1;
        g_menc[node * 2]     = encf(lrelu(as0 + ad0));   // self-loop seeds the max
        g_menc[node * 2 + 1] = encf(lrelu(as1 + ad1));
    }
}

__global__ void k_gat_max(const void* __restrict__ ei, int E) {
    int e = blockIdx.x * blockDim.x + threadIdx.x;
    if (e >= E) return;
    int r, c; load_edge(ei, e, E, r, c);
#pragma unroll
    for (int h = 0; h < 2; h++) {
        float v = lrelu(g_asrc[r * 2 + h] + g_adst[c * 2 + h]);
        atomicMax(&g_menc[c * 2 + h], encf(v));
    }
}

// warp per edge: exp-sum + message scatter (unnormalized; divide in finalize)
__global__ void k_gat_msg(const void* __restrict__ ei, int E) {
    int gid = blockIdx.x * blockDim.x + threadIdx.x;
    int ed = gid >> 5, lane = gid & 31;
    if (ed >= E) return;
    int r, c; load_edge(ei, ed, E, r, c);
    float e0 = lrelu(g_asrc[r * 2]     + g_adst[c * 2]);
    float e1 = lrelu(g_asrc[r * 2 + 1] + g_adst[c * 2 + 1]);
    float ex0 = __expf(e0 - decf(g_menc[c * 2]));
    float ex1 = __expf(e1 - decf(g_menc[c * 2 + 1]));
    float hg0 = g_hg[r * 64 + lane];
    float hg1 = g_hg[r * 64 + 32 + lane];
    atomicAdd(&g_accmsg[c * 64 + lane],      ex0 * hg0);
    atomicAdd(&g_accmsg[c * 64 + 32 + lane], ex1 * hg1);
    if (lane == 0) {
        atomicAdd(&g_s[c * 2],     ex0);
        atomicAdd(&g_s[c * 2 + 1], ex1);
    }
}

// warp per node: GAT finalize (softmax norm, mean heads, +b, relu), then z = dinv * (h2@W2)
__global__ void k_gat_fin(const float* __restrict__ gat_b, const float* __restrict__ W2, int n) {
    int gid = blockIdx.x * blockDim.x + threadIdx.x;
    int node = gid >> 5, lane = gid & 31;
    if (node >= n) return;
    float es0 = lrelu(g_asrc[node * 2]     + g_adst[node * 2]);
    float es1 = lrelu(g_asrc[node * 2 + 1] + g_adst[node * 2 + 1]);
    float exs0 = __expf(es0 - decf(g_menc[node * 2]));
    float exs1 = __expf(es1 - decf(g_menc[node * 2 + 1]));
    float s0 = g_s[node * 2]     + exs0;
    float s1 = g_s[node * 2 + 1] + exs1;
    float h0 = (g_accmsg[node * 64 + lane]      + exs0 * g_hg[node * 64 + lane])      / s0;
    float h1 = (g_accmsg[node * 64 + 32 + lane] + exs1 * g_hg[node * 64 + 32 + lane]) / s1;
    float h2 = fmaxf(fmaf(0.5f, h0 + h1, gat_b[lane]), 0.f);
    float zi = h2 * W2[lane];
#pragma unroll
    for (int off = 16; off; off >>= 1)
        zi += __shfl_down_sync(0xffffffffu, zi, off);
    if (lane == 0) g_z[node] = g_dinv[node] * zi;
}

__global__ void k_gcn2_edge(const void* __restrict__ ei, int E) {
    int e = blockIdx.x * blockDim.x + threadIdx.x;
    if (e >= E) return;
    int r, c; load_edge(ei, e, E, r, c);
    atomicAdd(&g_accz[c], g_z[r]);
}

__global__ void k_final(float* __restrict__ out, const float* __restrict__ b2, int n) {
    int node = blockIdx.x * blockDim.x + threadIdx.x;
    if (node >= n) return;
    out[node] = fmaf(g_dinv[node], g_accz[node] + g_z[node], b2[0]);
}

// ---------------- launch ----------------
extern "C" void kernel_launch(void* const* d_in, const int* in_sizes, int n_in,
                              void* d_out, int out_size) {
    const float* x    = (const float*)d_in[0];
    const void*  ei   = d_in[1];
    const float* W1   = (const float*)d_in[2];
    const float* b1   = (const float*)d_in[3];
    const float* Wg   = (const float*)d_in[4];
    const float* attS = (const float*)d_in[5];
    const float* attD = (const float*)d_in[6];
    const float* gb   = (const float*)d_in[7];
    const float* W2   = (const float*)d_in[8];
    const float* b2   = (const float*)d_in[9];
    float* out = (float*)d_out;

    int n = in_sizes[0] / 2;
    int E = in_sizes[1] / 2;
    const int T = 256;

    k_detect<<<1, 32>>>((const int*)ei);
    k_zero<<<(n * 64 + T - 1) / T, T>>>(n);
    k_degcount<<<(E + T - 1) / T, T>>>(ei, E);
    k_node1<<<(n * 32 + T - 1) / T, T>>>(x, W1, n);
    k_gcn1_edge<<<(int)(((long long)E * 32 + T - 1) / T), T>>>(ei, E);
    k_gat_node<<<(n * 32 + 127) / 128, 128>>>(Wg, b1, attS, attD, n);
    k_gat_max<<<(E + T - 1) / T, T>>>(ei, E);
    k_gat_msg<<<(int)(((long long)E * 32 + T - 1) / T), T>>>(ei, E);
    k_gat_fin<<<(n * 32 + T - 1) / T, T>>>(gb, W2, n);
    k_gcn2_edge<<<(E + T - 1) / T, T>>>(ei, E);
    k_final<<<(n + T - 1) / T, T>>>(out, b2, n);
}

// round 2
// speedup vs baseline: 2.1116x; 2.1116x over previous
#include <cuda_runtime.h>
#include <cuda_bf16.h>

// RoadGNN: GCN(2->32) -> ReLU -> GAT(32->2x32, mean heads) -> ReLU -> GCN(32->1)
// CSR-gather formulation: build CSR (by dst) once per call, then all three
// aggregation layers are warp-per-node gathers (no float atomics).

#define MAXN 100000
#define MAXE 1600000

// ---------------- scratch (device globals; no allocations) ----------------
__device__ int      g_deg[MAXN];       // in-degree (without self-loop)
__device__ int      g_off[MAXN];       // CSR offsets (exclusive scan of deg)
__device__ int      g_cur[MAXN];       // bucket cursors
__device__ int      g_csr[MAXE];       // row (src) ids grouped by col (dst)
__device__ int      g_bsum[128];       // scan block sums
__device__ float    g_dinv[MAXN];
__device__ float    g_hs[MAXN * 32];   // dinv[n] * (x@W1)[n]
__device__ float    g_hg[MAXN * 64];   // GAT linear output [N, 2*32]
__device__ float    g_asrc[MAXN * 2];
__device__ float    g_adst[MAXN * 2];
__device__ float    g_z[MAXN];         // dinv[n] * (h2 @ W2)[n]
__device__ int      g_is64;

// ---------------- helpers ----------------
__device__ __forceinline__ float lrelu(float v) { return v > 0.f ? v : 0.2f * v; }

__device__ __forceinline__ void load_edge(const void* ei, int e, int E, int& r, int& c) {
    if (g_is64) {
        const long long* p = (const long long*)ei;
        r = (int)p[e]; c = (int)p[E + e];
    } else {
        const int* p = (const int*)ei;
        r = p[e]; c = p[E + e];
    }
}

// ---------------- kernels ----------------

// Detect int64 vs int32 edge_index: int64 nonneg < 2^31 => odd int32 words are 0.
__global__ void k_detect(const int* __restrict__ ei32) {
    if (threadIdx.x == 0) {
        int is64 = 1;
        for (int i = 0; i < 64; i++)
            if (ei32[2 * i + 1] != 0) { is64 = 0; break; }
        g_is64 = is64;
    }
}

__global__ void k_zero(int n) {
    int gid = blockIdx.x * blockDim.x + threadIdx.x;
    if (gid < n) { g_deg[gid] = 0; g_cur[gid] = 0; }
}

__global__ void k_degcount(const void* __restrict__ ei, int E) {
    int e = blockIdx.x * blockDim.x + threadIdx.x;
    if (e >= E) return;
    int r, c; load_edge(ei, e, E, r, c);
    atomicAdd(&g_deg[c], 1);
}

// exclusive prefix scan of g_deg into g_off: 3 stages.
__global__ void k_scan1(int n) {
    __shared__ int sh[1024];
    int tid = threadIdx.x;
    int i = blockIdx.x * 1024 + tid;
    int v = (i < n) ? g_deg[i] : 0;
    sh[tid] = v;
    __syncthreads();
#pragma unroll
    for (int d = 1; d < 1024; d <<= 1) {
        int t = (tid >= d) ? sh[tid - d] : 0;
        __syncthreads();
        sh[tid] += t;
        __syncthreads();
    }
    if (i < n) g_off[i] = sh[tid] - v;          // exclusive within block
    if (tid == 1023) g_bsum[blockIdx.x] = sh[1023];
}

__global__ void k_scan2(int nb) {
    if (threadIdx.x == 0) {
        int run = 0;
        for (int b = 0; b < nb; b++) { int t = g_bsum[b]; g_bsum[b] = run; run += t; }
    }
}

__global__ void k_scan3(int n) {
    int i = blockIdx.x * 1024 + threadIdx.x;
    if (i < n) g_off[i] += g_bsum[blockIdx.x];
}

__global__ void k_fill(const void* __restrict__ ei, int E) {
    int e = blockIdx.x * blockDim.x + threadIdx.x;
    if (e >= E) return;
    int r, c; load_edge(ei, e, E, r, c);
    int pos = g_off[c] + atomicAdd(&g_cur[c], 1);
    g_csr[pos] = r;
}

// per-(node,channel): dinv = (deg+1)^-0.5, hs = dinv * (x@W1)
__global__ void k_node1(const float* __restrict__ x, const float* __restrict__ W1, int n) {
    int gid = blockIdx.x * blockDim.x + threadIdx.x;
    if (gid >= n * 32) return;
    int node = gid >> 5, k = gid & 31;
    float d = rsqrtf((float)(g_deg[node] + 1));
    if (k == 0) g_dinv[node] = d;
    float hp = fmaf(x[2 * node], W1[k], x[2 * node + 1] * W1[32 + k]);
    g_hs[gid] = d * hp;
}

// warp per node: GCN1 gather + relu, GAT linear (32x64 via shfl), attention dots.
__global__ void k_layer1(const float* __restrict__ Wg, const float* __restrict__ b1,
                         const float* __restrict__ attS, const float* __restrict__ attD, int n) {
    __shared__ float sWg[32 * 64];
    int tid = threadIdx.x;
    for (int i = tid; i < 2048; i += blockDim.x) sWg[i] = Wg[i];
    __syncthreads();
    int node = (blockIdx.x * blockDim.x + tid) >> 5;
    int lane = tid & 31;
    if (node >= n) return;

    float acc = g_hs[node * 32 + lane];          // self loop
    float acc2 = 0.f;
    int off = g_off[node], end = off + g_deg[node];
    int j = off;
    for (; j + 1 < end; j += 2) {
        int r0 = g_csr[j], r1 = g_csr[j + 1];
        acc  += g_hs[r0 * 32 + lane];
        acc2 += g_hs[r1 * 32 + lane];
    }
    if (j < end) acc += g_hs[g_csr[j] * 32 + lane];
    acc += acc2;

    float h1 = fmaxf(fmaf(g_dinv[node], acc, b1[lane]), 0.f);

    float o0 = 0.f, o1 = 0.f;
#pragma unroll
    for (int i = 0; i < 32; i++) {
        float hv = __shfl_sync(0xffffffffu, h1, i);
        o0 = fmaf(hv, sWg[i * 64 + lane], o0);
        o1 = fmaf(hv, sWg[i * 64 + 32 + lane], o1);
    }
    g_hg[node * 64 + lane]      = o0;
    g_hg[node * 64 + 32 + lane] = o1;

    float as0 = o0 * attS[lane];
    float as1 = o1 * attS[32 + lane];
    float ad0 = o0 * attD[lane];
    float ad1 = o1 * attD[32 + lane];
#pragma unroll
    for (int o = 16; o; o >>= 1) {
        as0 += __shfl_down_sync(0xffffffffu, as0, o);
        as1 += __shfl_down_sync(0xffffffffu, as1, o);
        ad0 += __shfl_down_sync(0xffffffffu, ad0, o);
        ad1 += __shfl_down_sync(0xffffffffu, ad1, o);
    }
    if (lane == 0) {
        g_asrc[node * 2]     = as0;
        g_asrc[node * 2 + 1] = as1;
        g_adst[node * 2]     = ad0;
        g_adst[node * 2 + 1] = ad1;
    }
}

// warp per node: GAT softmax + aggregate + finalize + z = dinv*(h2@W2)
__global__ void k_gat(const float* __restrict__ gat_b, const float* __restrict__ W2, int n) {
    int tid = threadIdx.x;
    int node = (blockIdx.x * blockDim.x + tid) >> 5;
    int lane = tid & 31;
    if (node >= n) return;

    float ad0 = g_adst[2 * node], ad1 = g_adst[2 * node + 1];
    float es0 = lrelu(g_asrc[2 * node]     + ad0);
    float es1 = lrelu(g_asrc[2 * node + 1] + ad1);
    int off = g_off[node], end = off + g_deg[node];

    // pass 1: segment max (lanes stride edges)
    float m0 = es0, m1 = es1;
    for (int j = off + lane; j < end; j += 32) {
        int r = g_csr[j];
        float2 as = *(const float2*)&g_asrc[2 * r];
        m0 = fmaxf(m0, lrelu(as.x + ad0));
        m1 = fmaxf(m1, lrelu(as.y + ad1));
    }
#pragma unroll
    for (int o = 16; o; o >>= 1) {
        m0 = fmaxf(m0, __shfl_xor_sync(0xffffffffu, m0, o));
        m1 = fmaxf(m1, __shfl_xor_sync(0xffffffffu, m1, o));
    }

    // pass 2: exp-weighted aggregation (all lanes per edge; lane = channel)
    float exs0 = __expf(es0 - m0), exs1 = __expf(es1 - m1);
    float s0 = exs0, s1 = exs1;
    float acc0 = exs0 * g_hg[node * 64 + lane];
    float acc1 = exs1 * g_hg[node * 64 + 32 + lane];
    for (int j = off; j < end; j++) {
        int r = g_csr[j];                         // broadcast load
        float2 as = *(const float2*)&g_asrc[2 * r];
        float ex0 = __expf(lrelu(as.x + ad0) - m0);
        float ex1 = __expf(lrelu(as.y + ad1) - m1);
        acc0 = fmaf(ex0, g_hg[r * 64 + lane],      acc0);
        acc1 = fmaf(ex1, g_hg[r * 64 + 32 + lane], acc1);
        s0 += ex0; s1 += ex1;
    }

    float h2 = fmaxf(fmaf(0.5f, acc0 / s0 + acc1 / s1, gat_b[lane]), 0.f);
    float zi = h2 * W2[lane];
#pragma unroll
    for (int o = 16; o; o >>= 1)
        zi += __shfl_down_sync(0xffffffffu, zi, o);
    if (lane == 0) g_z[node] = g_dinv[node] * zi;
}

// warp per node: GCN2 gather + output
__global__ void k_gcn2(float* __restrict__ out, const float* __restrict__ b2, int n) {
    int tid = threadIdx.x;
    int node = (blockIdx.x * blockDim.x + tid) >> 5;
    int lane = tid & 31;
    if (node >= n) return;
    float s = (lane == 0) ? g_z[node] : 0.f;
    int off = g_off[node], end = off + g_deg[node];
    for (int j = off + lane; j < end; j += 32)
        s += g_z[g_csr[j]];
#pragma unroll
    for (int o = 16; o; o >>= 1)
        s += __shfl_down_sync(0xffffffffu, s, o);
    if (lane == 0) out[node] = fmaf(g_dinv[node], s, b2[0]);
}

// ---------------- launch ----------------
extern "C" void kernel_launch(void* const* d_in, const int* in_sizes, int n_in,
                              void* d_out, int out_size) {
    const float* x    = (const float*)d_in[0];
    const void*  ei   = d_in[1];
    const float* W1   = (const float*)d_in[2];
    const float* b1   = (const float*)d_in[3];
    const float* Wg   = (const float*)d_in[4];
    const float* attS = (const float*)d_in[5];
    const float* attD = (const float*)d_in[6];
    const float* gb   = (const float*)d_in[7];
    const float* W2   = (const float*)d_in[8];
    const float* b2   = (const float*)d_in[9];
    float* out = (float*)d_out;

    int n = in_sizes[0] / 2;
    int E = in_sizes[1] / 2;
    const int T = 256;
    int nb = (n + 1023) / 1024;

    k_detect<<<1, 32>>>((const int*)ei);
    k_zero<<<(n + T - 1) / T, T>>>(n);
    k_degcount<<<(E + T - 1) / T, T>>>(ei, E);
    k_scan1<<<nb, 1024>>>(n);
    k_scan2<<<1, 32>>>(nb);
    k_scan3<<<nb, 1024>>>(n);
    k_fill<<<(E + T - 1) / T, T>>>(ei, E);
    k_node1<<<(n * 32 + T - 1) / T, T>>>(x, W1, n);
    k_layer1<<<(n * 32 + T - 1) / T, T>>>(Wg, b1, attS, attD, n);
    k_gat<<<(n * 32 + T - 1) / T, T>>>(gb, W2, n);
    k_gcn2<<<(n * 32 + T - 1) / T, T>>>(out, b2, n);
}